// round 10
// baseline (speedup 1.0000x reference)
#include <cuda_runtime.h>
#include <cuda_bf16.h>
#include <math.h>
#include <stdint.h>

#define N_PTS 8192
#define M_PTS 2048
#define K_LAST 10
#define VARS 3

typedef unsigned long long u64;

// ---------------- packed f32x2 helpers ----------------
__device__ __forceinline__ u64 pk2(float lo, float hi) {
    u64 r; asm("mov.b64 %0,{%1,%2};" : "=l"(r) : "f"(lo), "f"(hi)); return r;
}
__device__ __forceinline__ u64 dup2(float x) { return pk2(x, x); }
__device__ __forceinline__ void unpk2(u64 v, float& lo, float& hi) {
    asm("mov.b64 {%0,%1},%2;" : "=f"(lo), "=f"(hi) : "l"(v));
}
__device__ __forceinline__ u64 f2fma(u64 a, u64 b, u64 c) {
    u64 d; asm("fma.rn.f32x2 %0,%1,%2,%3;" : "=l"(d) : "l"(a), "l"(b), "l"(c)); return d;
}
__device__ __forceinline__ u64 f2mul(u64 a, u64 b) {
    u64 d; asm("mul.rn.f32x2 %0,%1,%2;" : "=l"(d) : "l"(a), "l"(b)); return d;
}

__device__ __forceinline__ float gelu(float x) {
    return 0.5f * x * (1.0f + erff(x * 0.70710678118654752f));
}

// packed GELU (A&S 7.1.26 erf, abs err <= 1.5e-7)
__device__ __forceinline__ u64 gelu2(u64 x) {
    u64 ax = x & 0x7FFFFFFF7FFFFFFFULL;
    u64 z  = f2mul(ax, dup2(0.70710678118654752f));
    u64 den = f2fma(z, dup2(0.3275911f), dup2(1.0f));
    float dl, dh, rl, rh;
    unpk2(den, dl, dh);
    asm("rcp.approx.f32 %0,%1;" : "=f"(rl) : "f"(dl));
    asm("rcp.approx.f32 %0,%1;" : "=f"(rh) : "f"(dh));
    u64 t = pk2(rl, rh);
    u64 z2 = f2mul(z, z);
    u64 m  = f2mul(z2, dup2(-1.4426950408889634f));
    float ml, mh, el, eh;
    unpk2(m, ml, mh);
    asm("ex2.approx.f32 %0,%1;" : "=f"(el) : "f"(ml));
    asm("ex2.approx.f32 %0,%1;" : "=f"(eh) : "f"(mh));
    u64 e = pk2(el, eh);
    u64 p = f2fma(t, dup2(1.061405429f), dup2(-1.453152027f));
    p = f2fma(p, t, dup2(1.421413741f));
    p = f2fma(p, t, dup2(-0.284496736f));
    p = f2fma(p, t, dup2(0.254829592f));
    p = f2mul(p, t);
    u64 np = p ^ 0x8000000080000000ULL;
    u64 u  = f2fma(np, e, dup2(1.0f));
    u64 E  = u | (x & 0x8000000080000000ULL);
    u64 h  = f2fma(E, dup2(0.5f), dup2(0.5f));
    return f2mul(x, h);
}

// pack two floats to bf16x2 (a -> low 16 bits, b -> high)
__device__ __forceinline__ uint32_t pack_bf16(float a, float b) {
    uint32_t r; asm("cvt.rn.bf16x2.f32 %0, %1, %2;" : "=r"(r) : "f"(b), "f"(a));
    return r;
}
// split f32 pair into (hi bf16x2, lo bf16x2)
__device__ __forceinline__ void split_pack(float f0, float f1, uint32_t& hi, uint32_t& lo) {
    hi = pack_bf16(f0, f1);
    float h0 = __uint_as_float(hi << 16);
    float h1 = __uint_as_float(hi & 0xFFFF0000u);
    lo = pack_bf16(f0 - h0, f1 - h1);
}

// m16n8k16 bf16 MMA, D (f32) accumulate in place
__device__ __forceinline__ void mma16816(float* d, const uint32_t* a, uint32_t b0, uint32_t b1) {
    asm volatile(
        "mma.sync.aligned.m16n8k16.row.col.f32.bf16.bf16.f32 "
        "{%0,%1,%2,%3}, {%4,%5,%6,%7}, {%8,%9}, {%0,%1,%2,%3};"
        : "+f"(d[0]), "+f"(d[1]), "+f"(d[2]), "+f"(d[3])
        : "r"(a[0]), "r"(a[1]), "r"(a[2]), "r"(a[3]), "r"(b0), "r"(b1));
}

// ---------------- scratch ----------------
__device__ float g_f0[VARS * N_PTS * 32];
__device__ float g_acc[VARS * N_PTS * 32];
__device__ uint8_t g_blob[2][46080];
// blob layout (bytes): L1 = f-rows only (K=32, 2 k-tiles)
#define BL1H 0        // 20 sets * 256
#define BL1L 5120
#define BL2H 10240    // 50 sets * 256
#define BL2L 23040
#define BL3H 35840    // 20 sets * 256
#define BL3L 40960
#define BLOB_BYTES 46080

// ---------------- fused weight prep: all 6 jobs in one launch ----------------
// Fragment set (kt,nt): lane holds n = nt*8+lane/4, k0 = kt*16+2*(lane%4):
// reg0={W[k0][n],W[k0+1][n]}, reg1={W[k0+8][n],W[k0+9][n]}.
__global__ void prep_all_kernel(const float* __restrict__ W10, const float* __restrict__ W11,
                                const float* __restrict__ W12,
                                const float* __restrict__ W20, const float* __restrict__ W21,
                                const float* __restrict__ W22,
                                uint8_t* __restrict__ blob0, uint8_t* __restrict__ blob1) {
    int idx = blockIdx.x * 256 + threadIdx.x;
    if (idx >= 2 * 90 * 32) return;
    int lane = idx & 31;
    int set = (idx >> 5) % 90;
    int phase = (idx >> 5) / 90;
    uint8_t* blob = phase ? blob1 : blob0;

    const float* W; int NT, N, Kreal, sl, oh, ol;
    if (set < 20)      { W = (phase ? W20 : W10) + 4 * 80; NT = 10; N = 80; Kreal = 32; sl = set;      oh = BL1H; ol = BL1L; }
    else if (set < 70) { W = phase ? W21 : W11;            NT = 10; N = 80; Kreal = 80; sl = set - 20; oh = BL2H; ol = BL2L; }
    else               { W = phase ? W22 : W12;            NT = 4;  N = 32; Kreal = 80; sl = set - 70; oh = BL3H; ol = BL3L; }

    int kt = sl / NT, nt = sl - kt * NT;
    int n = nt * 8 + (lane >> 2);
    int k0 = kt * 16 + 2 * (lane & 3);
    float v[4];
#pragma unroll
    for (int j = 0; j < 4; j++) {
        int k = k0 + (j >> 1) * 8 + (j & 1);
        v[j] = (k < Kreal) ? W[k * N + n] : 0.f;
    }
    uint32_t h0, l0, h1, l1;
    split_pack(v[0], v[1], h0, l0);
    split_pack(v[2], v[3], h1, l1);
    *(u64*)(blob + oh + (size_t)sl * 256 + lane * 8) = (u64)h0 | ((u64)h1 << 32);
    *(u64*)(blob + ol + (size_t)sl * 256 + lane * 8) = (u64)l0 | ((u64)l1 << 32);
}

// ---------------- projection MLP ----------------
__global__ void proj_kernel(const float* __restrict__ inp,
                            const float* __restrict__ W0, const float* __restrict__ b0,
                            const float* __restrict__ W1, const float* __restrict__ b1,
                            float* __restrict__ f0) {
    __shared__ float hs[4][64];
    int warp = threadIdx.x >> 5, lane = threadIdx.x & 31;
    int pv = blockIdx.x * 4 + warp;
    if (pv >= VARS * N_PTS) return;
    int v = pv / N_PTS, n = pv - v * N_PTS;
    const float* x = inp + n * (VARS * 8) + v * 8;
    float xr[8];
#pragma unroll
    for (int i = 0; i < 8; i++) xr[i] = x[i];
    float a0 = b0[lane], a1 = b0[lane + 32];
#pragma unroll
    for (int i = 0; i < 8; i++) {
        a0 = fmaf(xr[i], W0[i * 64 + lane], a0);
        a1 = fmaf(xr[i], W0[i * 64 + lane + 32], a1);
    }
    hs[warp][lane]      = gelu(a0);
    hs[warp][lane + 32] = gelu(a1);
    __syncwarp();
    float acc = b1[lane];
#pragma unroll
    for (int h = 0; h < 64; h++) acc = fmaf(hs[warp][h], W1[h * 32 + lane], acc);
    f0[(size_t)pv * 32 + lane] = acc;
}

// ---------------- HMMA edge MLP ----------------
// Input layout per edge row in xst: cols 0..31 = f[nbr], cols 32..35 = positions.
// Layer 1 = 2 bf16 k-tiles (f) + exact fp32 FFMA tail (positions, 4x80 table).
#define TPB 128
#define SM_PTAB  46080          // 320 floats (W0 rows 0..3, fp32)
#define SM_BS0   47360
#define SM_BS1   47680
#define SM_BS2   48000
#define SM_XST   48128          // + warp*3072 (16 rows x 48 floats)
#define SM_SEG   60416          // + warp*64
#define SMEM_BYTES 60672

template <int MODE>
__global__ void __launch_bounds__(TPB, 3)
edge_mma_kernel(const uint8_t* __restrict__ blob, const float* __restrict__ W0g,
                const float* __restrict__ b0g, const float* __restrict__ b1g,
                const float* __restrict__ b2g,
                const float* __restrict__ grid_in, const float* __restrict__ grid_out,
                const float* __restrict__ fsrc,
                const int* __restrict__ idxA, const int* __restrict__ idxB,
                float* __restrict__ outbuf, int E) {
    extern __shared__ __align__(16) uint8_t sm[];
    int tid = threadIdx.x;
    int warp = tid >> 5, lane = tid & 31;
    int g = lane >> 2;          // row group 0..7
    int t = lane & 3;           // thread-in-group
    int v = blockIdx.y;

    // stage blob + position table + biases
    {
        const uint4* src = (const uint4*)blob;
        uint4* dst = (uint4*)sm;
        for (int i = tid; i < BLOB_BYTES / 16; i += TPB) dst[i] = src[i];
        float* ptab = (float*)(sm + SM_PTAB);
        for (int i = tid; i < 320; i += TPB) ptab[i] = W0g[i];   // rows 0..3
        float* bs0 = (float*)(sm + SM_BS0);
        float* bs1 = (float*)(sm + SM_BS1);
        float* bs2 = (float*)(sm + SM_BS2);
        if (tid < 80) { bs0[tid] = b0g[tid]; bs1[tid] = b1g[tid]; }
        if (tid < 32) bs2[tid] = b2g[tid];
    }
    __syncthreads();

    float* xst = (float*)(sm + SM_XST + warp * 3072);
    int*   seg_sh = (int*)(sm + SM_SEG + warp * 64);
    const float* ptab = (const float*)(sm + SM_PTAB);
    const float* bs0 = (const float*)(sm + SM_BS0);
    const float* bs1 = (const float*)(sm + SM_BS1);
    const float* bs2 = (const float*)(sm + SM_BS2);

#pragma unroll 1
    for (int mt = 0; mt < 2; mt++) {
        int tileBase = blockIdx.x * 128 + warp * 32 + mt * 16;

        // ---- gather: 2 lanes per edge; f -> cols 0..31, pos -> cols 32..35 ----
        {
            int el = lane & 15, half = lane >> 4;
            int e = tileBase + el;
            bool gv = e < E;
            int ee = gv ? e : 0;
            int jn = idxA[ee];
            int sg = (MODE == 0) ? idxB[ee] : ee / K_LAST;
            float* xrow = xst + el * 48;
            if (half == 0) {
                seg_sh[el] = gv ? sg : -1;
                float p0 = 0, p1 = 0, p2 = 0, p3 = 0;
                if (gv) {
                    p0 = grid_in[2 * jn]; p1 = grid_in[2 * jn + 1];
                    if (MODE == 0) { p2 = grid_in[2 * sg];  p3 = grid_in[2 * sg + 1]; }
                    else           { p2 = grid_out[2 * sg]; p3 = grid_out[2 * sg + 1]; }
                }
                xrow[32] = p0; xrow[33] = p1; xrow[34] = p2; xrow[35] = p3;
            }
            const float4* fp = (const float4*)(fsrc + ((size_t)v * N_PTS + jn) * 32 + half * 16);
            float4* xd = (float4*)(xrow + 16 * half);
            xd[0] = fp[0]; xd[1] = fp[1]; xd[2] = fp[2]; xd[3] = fp[3];
        }
        __syncwarp();

        // ---- A1 fragments (f part, 2 k-tiles) + position scalars ----
        uint32_t a1h[2][4], a1l[2][4];
#pragma unroll
        for (int kt = 0; kt < 2; kt++) {
#pragma unroll
            for (int rr = 0; rr < 4; rr++) {
                int row = g + (rr & 1) * 8;
                int col = 16 * kt + 2 * t + (rr >> 1) * 8;
                u64 pv_ = *(const u64*)(xst + row * 48 + col);
                float f0, f1; unpk2(pv_, f0, f1);
                split_pack(f0, f1, a1h[kt][rr], a1l[kt][rr]);
            }
        }
        float px0[4], px1[4];
#pragma unroll
        for (int k = 0; k < 4; k++) {
            px0[k] = xst[g * 48 + 32 + k];
            px1[k] = xst[(g + 8) * 48 + 32 + k];
        }

        // ---- layer 1: K=32 via MMA + exact fp32 position tail ----
        float d1[10][4];
#pragma unroll
        for (int nt = 0; nt < 10; nt++) {
            float* d = d1[nt];
            d[0] = 0.f; d[1] = 0.f; d[2] = 0.f; d[3] = 0.f;
#pragma unroll
            for (int kt = 0; kt < 2; kt++) {
                int set = kt * 10 + nt;
                u64 bh = *(const u64*)(sm + BL1H + (size_t)set * 256 + lane * 8);
                u64 bl = *(const u64*)(sm + BL1L + (size_t)set * 256 + lane * 8);
                uint32_t bh0 = (uint32_t)bh, bh1 = (uint32_t)(bh >> 32);
                uint32_t bl0 = (uint32_t)bl, bl1 = (uint32_t)(bl >> 32);
                mma16816(d, a1h[kt], bh0, bh1);
                mma16816(d, a1h[kt], bl0, bl1);
                mma16816(d, a1l[kt], bh0, bh1);
            }
#pragma unroll
            for (int k = 0; k < 4; k++) {
                u64 wv = *(const u64*)(ptab + k * 80 + nt * 8 + 2 * t);
                float w0, w1; unpk2(wv, w0, w1);
                d[0] = fmaf(px0[k], w0, d[0]); d[1] = fmaf(px0[k], w1, d[1]);
                d[2] = fmaf(px1[k], w0, d[2]); d[3] = fmaf(px1[k], w1, d[3]);
            }
        }

        // ---- epilogue 1: bias + gelu + split -> A2 fragments ----
        uint32_t a2h[5][4], a2l[5][4];
#pragma unroll
        for (int m = 0; m < 5; m++) {
            int j0 = 2 * m, j1 = 2 * m + 1;
            float bb0, bb1, bb2, bb3;
            unpk2(*(const u64*)(bs0 + 8 * j0 + 2 * t), bb0, bb1);
            unpk2(*(const u64*)(bs0 + 8 * j1 + 2 * t), bb2, bb3);
            float q0, q1;
            unpk2(gelu2(pk2(d1[j0][0] + bb0, d1[j0][1] + bb1)), q0, q1);
            split_pack(q0, q1, a2h[m][0], a2l[m][0]);
            unpk2(gelu2(pk2(d1[j0][2] + bb0, d1[j0][3] + bb1)), q0, q1);
            split_pack(q0, q1, a2h[m][1], a2l[m][1]);
            unpk2(gelu2(pk2(d1[j1][0] + bb2, d1[j1][1] + bb3)), q0, q1);
            split_pack(q0, q1, a2h[m][2], a2l[m][2]);
            unpk2(gelu2(pk2(d1[j1][2] + bb2, d1[j1][3] + bb3)), q0, q1);
            split_pack(q0, q1, a2h[m][3], a2l[m][3]);
        }

        // ---- layer 2: K=80, N=80 ----
        float d2[10][4];
#pragma unroll
        for (int nt = 0; nt < 10; nt++) {
            float* d = d2[nt];
            d[0] = 0.f; d[1] = 0.f; d[2] = 0.f; d[3] = 0.f;
#pragma unroll
            for (int kt = 0; kt < 5; kt++) {
                int set = kt * 10 + nt;
                u64 bh = *(const u64*)(sm + BL2H + (size_t)set * 256 + lane * 8);
                u64 bl = *(const u64*)(sm + BL2L + (size_t)set * 256 + lane * 8);
                uint32_t bh0 = (uint32_t)bh, bh1 = (uint32_t)(bh >> 32);
                uint32_t bl0 = (uint32_t)bl, bl1 = (uint32_t)(bl >> 32);
                mma16816(d, a2h[kt], bh0, bh1);
                mma16816(d, a2h[kt], bl0, bl1);
                mma16816(d, a2l[kt], bh0, bh1);
            }
        }

        // ---- epilogue 2 -> A3 fragments ----
        uint32_t a3h[5][4], a3l[5][4];
#pragma unroll
        for (int m = 0; m < 5; m++) {
            int j0 = 2 * m, j1 = 2 * m + 1;
            float bb0, bb1, bb2, bb3;
            unpk2(*(const u64*)(bs1 + 8 * j0 + 2 * t), bb0, bb1);
            unpk2(*(const u64*)(bs1 + 8 * j1 + 2 * t), bb2, bb3);
            float q0, q1;
            unpk2(gelu2(pk2(d2[j0][0] + bb0, d2[j0][1] + bb1)), q0, q1);
            split_pack(q0, q1, a3h[m][0], a3l[m][0]);
            unpk2(gelu2(pk2(d2[j0][2] + bb0, d2[j0][3] + bb1)), q0, q1);
            split_pack(q0, q1, a3h[m][1], a3l[m][1]);
            unpk2(gelu2(pk2(d2[j1][0] + bb2, d2[j1][1] + bb3)), q0, q1);
            split_pack(q0, q1, a3h[m][2], a3l[m][2]);
            unpk2(gelu2(pk2(d2[j1][2] + bb2, d2[j1][3] + bb3)), q0, q1);
            split_pack(q0, q1, a3h[m][3], a3l[m][3]);
        }

        // ---- layer 3: K=80, N=32 ----
        float d3[4][4];
#pragma unroll
        for (int nt = 0; nt < 4; nt++) {
            float* d = d3[nt];
            d[0] = 0.f; d[1] = 0.f; d[2] = 0.f; d[3] = 0.f;
#pragma unroll
            for (int kt = 0; kt < 5; kt++) {
                int set = kt * 4 + nt;
                u64 bh = *(const u64*)(sm + BL3H + (size_t)set * 256 + lane * 8);
                u64 bl = *(const u64*)(sm + BL3L + (size_t)set * 256 + lane * 8);
                uint32_t bh0 = (uint32_t)bh, bh1 = (uint32_t)(bh >> 32);
                uint32_t bl0 = (uint32_t)bl, bl1 = (uint32_t)(bl >> 32);
                mma16816(d, a3h[kt], bh0, bh1);
                mma16816(d, a3h[kt], bl0, bl1);
                mma16816(d, a3l[kt], bh0, bh1);
            }
        }

        // ---- epilogue 3: bias + scatter (rows g and g+8) ----
        {
            int sg0 = seg_sh[g], sg1 = seg_sh[g + 8];
            float scale = (MODE == 0) ? 1.0f : 0.1f;
            float* dst0 = nullptr; float* dst1 = nullptr;
            if (MODE == 0) {
                if (sg0 >= 0) dst0 = outbuf + ((size_t)v * N_PTS + sg0) * 32;
                if (sg1 >= 0) dst1 = outbuf + ((size_t)v * N_PTS + sg1) * 32;
            } else {
                if (sg0 >= 0) dst0 = outbuf + (size_t)sg0 * (VARS * 32) + v * 32;
                if (sg1 >= 0) dst1 = outbuf + (size_t)sg1 * (VARS * 32) + v * 32;
            }
#pragma unroll
            for (int nt = 0; nt < 4; nt++) {
                float bb0, bb1;
                unpk2(*(const u64*)(bs2 + 8 * nt + 2 * t), bb0, bb1);
                int c0 = 8 * nt + 2 * t;
                if (dst0) {
                    atomicAdd(dst0 + c0,     (d3[nt][0] + bb0) * scale);
                    atomicAdd(dst0 + c0 + 1, (d3[nt][1] + bb1) * scale);
                }
                if (dst1) {
                    atomicAdd(dst1 + c0,     (d3[nt][2] + bb0) * scale);
                    atomicAdd(dst1 + c0 + 1, (d3[nt][3] + bb1) * scale);
                }
            }
        }
        __syncwarp();
    }
}

// f1 = segment_sum * inv_count + f0 (in place)
__global__ void f1_kernel(float* __restrict__ f0, const float* __restrict__ acc,
                          const int* __restrict__ counts) {
    int idx = blockIdx.x * 256 + threadIdx.x;
    if (idx >= VARS * N_PTS * 32) return;
    int n = (idx >> 5) % N_PTS;
    int c = counts[n];
    float inv = 1.0f / (float)(c > 1 ? c : 1);
    f0[idx] = fmaf(acc[idx], inv, f0[idx]);
}

extern "C" void kernel_launch(void* const* d_in, const int* in_sizes, int n_in,
                              void* d_out, int out_size) {
    const float* inp   = (const float*)d_in[0];
    const float* gin   = (const float*)d_in[1];
    const float* gout  = (const float*)d_in[2];
    const float* pW0   = (const float*)d_in[3];
    const float* pb0   = (const float*)d_in[4];
    const float* pW1   = (const float*)d_in[5];
    const float* pb1   = (const float*)d_in[6];
    const float* i0W0  = (const float*)d_in[7];
    const float* i0b0  = (const float*)d_in[8];
    const float* i0W1  = (const float*)d_in[9];
    const float* i0b1  = (const float*)d_in[10];
    const float* i0W2  = (const float*)d_in[11];
    const float* i0b2  = (const float*)d_in[12];
    const float* i1W0  = (const float*)d_in[13];
    const float* i1b0  = (const float*)d_in[14];
    const float* i1W1  = (const float*)d_in[15];
    const float* i1b1  = (const float*)d_in[16];
    const float* i1W2  = (const float*)d_in[17];
    const float* i1b2  = (const float*)d_in[18];
    const int* nbr_index  = (const int*)d_in[19];
    const int* nbr_seg    = (const int*)d_in[20];
    const int* nbr_counts = (const int*)d_in[21];
    const int* nbr_last   = (const int*)d_in[22];
    int E = in_sizes[19];

    float *f0, *acc;
    uint8_t* blob;
    cudaGetSymbolAddress((void**)&f0,   g_f0);
    cudaGetSymbolAddress((void**)&acc,  g_acc);
    cudaGetSymbolAddress((void**)&blob, g_blob);
    uint8_t* blob0 = blob;
    uint8_t* blob1 = blob + BLOB_BYTES;

    cudaMemsetAsync(acc, 0, sizeof(float) * VARS * N_PTS * 32);
    cudaMemsetAsync(d_out, 0, sizeof(float) * (size_t)out_size);

    // single fused prep launch (both phases, all 3 layers)
    prep_all_kernel<<<(2 * 90 * 32 + 255) / 256, 256>>>(i0W0, i0W1, i0W2,
                                                        i1W0, i1W1, i1W2, blob0, blob1);

    proj_kernel<<<(VARS * N_PTS + 3) / 4, 128>>>(inp, pW0, pb0, pW1, pb1, f0);

    cudaFuncSetAttribute(edge_mma_kernel<0>, cudaFuncAttributeMaxDynamicSharedMemorySize, SMEM_BYTES);
    cudaFuncSetAttribute(edge_mma_kernel<1>, cudaFuncAttributeMaxDynamicSharedMemorySize, SMEM_BYTES);

    dim3 g1((unsigned)((E + 127) / 128), VARS);
    edge_mma_kernel<0><<<g1, TPB, SMEM_BYTES>>>(blob0, i0W0, i0b0, i0b1, i0b2,
                                                gin, nullptr, f0, nbr_index, nbr_seg, acc, E);

    f1_kernel<<<(VARS * N_PTS * 32 + 255) / 256, 256>>>(f0, acc, nbr_counts);

    int E2 = M_PTS * K_LAST;
    dim3 g2((unsigned)((E2 + 127) / 128), VARS);
    edge_mma_kernel<1><<<g2, TPB, SMEM_BYTES>>>(blob1, i1W0, i1b0, i1b1, i1b2,
                                                gin, gout, f0, nbr_last, nullptr, (float*)d_out, E2);
}

// round 11
// speedup vs baseline: 1.0193x; 1.0193x over previous
#include <cuda_runtime.h>
#include <cuda_bf16.h>
#include <math.h>
#include <stdint.h>

#define N_PTS 8192
#define M_PTS 2048
#define K_LAST 10
#define VARS 3

typedef unsigned long long u64;

// ---------------- packed f32x2 helpers ----------------
__device__ __forceinline__ u64 pk2(float lo, float hi) {
    u64 r; asm("mov.b64 %0,{%1,%2};" : "=l"(r) : "f"(lo), "f"(hi)); return r;
}
__device__ __forceinline__ u64 dup2(float x) { return pk2(x, x); }
__device__ __forceinline__ void unpk2(u64 v, float& lo, float& hi) {
    asm("mov.b64 {%0,%1},%2;" : "=f"(lo), "=f"(hi) : "l"(v));
}
__device__ __forceinline__ u64 f2fma(u64 a, u64 b, u64 c) {
    u64 d; asm("fma.rn.f32x2 %0,%1,%2,%3;" : "=l"(d) : "l"(a), "l"(b), "l"(c)); return d;
}
__device__ __forceinline__ u64 f2mul(u64 a, u64 b) {
    u64 d; asm("mul.rn.f32x2 %0,%1,%2;" : "=l"(d) : "l"(a), "l"(b)); return d;
}

__device__ __forceinline__ float gelu(float x) {
    return 0.5f * x * (1.0f + erff(x * 0.70710678118654752f));
}

// packed GELU (A&S 7.1.26 erf, abs err <= 1.5e-7)
__device__ __forceinline__ u64 gelu2(u64 x) {
    u64 ax = x & 0x7FFFFFFF7FFFFFFFULL;
    u64 z  = f2mul(ax, dup2(0.70710678118654752f));
    u64 den = f2fma(z, dup2(0.3275911f), dup2(1.0f));
    float dl, dh, rl, rh;
    unpk2(den, dl, dh);
    asm("rcp.approx.f32 %0,%1;" : "=f"(rl) : "f"(dl));
    asm("rcp.approx.f32 %0,%1;" : "=f"(rh) : "f"(dh));
    u64 t = pk2(rl, rh);
    u64 z2 = f2mul(z, z);
    u64 m  = f2mul(z2, dup2(-1.4426950408889634f));
    float ml, mh, el, eh;
    unpk2(m, ml, mh);
    asm("ex2.approx.f32 %0,%1;" : "=f"(el) : "f"(ml));
    asm("ex2.approx.f32 %0,%1;" : "=f"(eh) : "f"(mh));
    u64 e = pk2(el, eh);
    u64 p = f2fma(t, dup2(1.061405429f), dup2(-1.453152027f));
    p = f2fma(p, t, dup2(1.421413741f));
    p = f2fma(p, t, dup2(-0.284496736f));
    p = f2fma(p, t, dup2(0.254829592f));
    p = f2mul(p, t);
    u64 np = p ^ 0x8000000080000000ULL;
    u64 u  = f2fma(np, e, dup2(1.0f));
    u64 E  = u | (x & 0x8000000080000000ULL);
    u64 h  = f2fma(E, dup2(0.5f), dup2(0.5f));
    return f2mul(x, h);
}

// pack two floats to bf16x2 (a -> low 16 bits, b -> high)
__device__ __forceinline__ uint32_t pack_bf16(float a, float b) {
    uint32_t r; asm("cvt.rn.bf16x2.f32 %0, %1, %2;" : "=r"(r) : "f"(b), "f"(a));
    return r;
}
// split f32 pair into (hi bf16x2, lo bf16x2)
__device__ __forceinline__ void split_pack(float f0, float f1, uint32_t& hi, uint32_t& lo) {
    hi = pack_bf16(f0, f1);
    float h0 = __uint_as_float(hi << 16);
    float h1 = __uint_as_float(hi & 0xFFFF0000u);
    lo = pack_bf16(f0 - h0, f1 - h1);
}

// m16n8k16 bf16 MMA, D (f32) accumulate in place
__device__ __forceinline__ void mma16816(float* d, const uint32_t* a, uint32_t b0, uint32_t b1) {
    asm volatile(
        "mma.sync.aligned.m16n8k16.row.col.f32.bf16.bf16.f32 "
        "{%0,%1,%2,%3}, {%4,%5,%6,%7}, {%8,%9}, {%0,%1,%2,%3};"
        : "+f"(d[0]), "+f"(d[1]), "+f"(d[2]), "+f"(d[3])
        : "r"(a[0]), "r"(a[1]), "r"(a[2]), "r"(a[3]), "r"(b0), "r"(b1));
}

// ---------------- scratch ----------------
__device__ float g_f0[VARS * N_PTS * 32];
__device__ float g_acc[VARS * N_PTS * 32];
__device__ uint8_t g_blob[2][51200];
// blob byte offsets (fragment-major weights, hi/lo):
#define BL1H 0        // 30 sets * 256
#define BL1L 7680
#define BL2H 15360    // 50 sets * 256
#define BL2L 28160
#define BL3H 40960    // 20 sets * 256
#define BL3L 46080
#define BLOB_BYTES 51200

// ---------------- fused weight prep: all 6 jobs, one launch ----------------
// Fragment set (kt,nt): lane holds n = nt*8+lane/4, k0 = kt*16+2*(lane%4):
// reg0={W[k0][n],W[k0+1][n]}, reg1={W[k0+8][n],W[k0+9][n]}.
__global__ void prep_all_kernel(const float* __restrict__ W10, const float* __restrict__ W11,
                                const float* __restrict__ W12,
                                const float* __restrict__ W20, const float* __restrict__ W21,
                                const float* __restrict__ W22,
                                uint8_t* __restrict__ blob0, uint8_t* __restrict__ blob1) {
    int idx = blockIdx.x * 256 + threadIdx.x;
    if (idx >= 2 * 100 * 32) return;
    int lane = idx & 31;
    int set = (idx >> 5) % 100;
    int phase = (idx >> 5) / 100;
    uint8_t* blob = phase ? blob1 : blob0;

    const float* W; int NT, N, Kreal, sl, oh, ol;
    if (set < 30)      { W = phase ? W20 : W10; NT = 10; N = 80; Kreal = 36; sl = set;      oh = BL1H; ol = BL1L; }
    else if (set < 80) { W = phase ? W21 : W11; NT = 10; N = 80; Kreal = 80; sl = set - 30; oh = BL2H; ol = BL2L; }
    else               { W = phase ? W22 : W12; NT = 4;  N = 32; Kreal = 80; sl = set - 80; oh = BL3H; ol = BL3L; }

    int kt = sl / NT, nt = sl - kt * NT;
    int n = nt * 8 + (lane >> 2);
    int k0 = kt * 16 + 2 * (lane & 3);
    float v[4];
#pragma unroll
    for (int j = 0; j < 4; j++) {
        int k = k0 + (j >> 1) * 8 + (j & 1);
        v[j] = (k < Kreal) ? W[k * N + n] : 0.f;
    }
    uint32_t h0, l0, h1, l1;
    split_pack(v[0], v[1], h0, l0);
    split_pack(v[2], v[3], h1, l1);
    *(u64*)(blob + oh + (size_t)sl * 256 + lane * 8) = (u64)h0 | ((u64)h1 << 32);
    *(u64*)(blob + ol + (size_t)sl * 256 + lane * 8) = (u64)l0 | ((u64)l1 << 32);
}

// ---------------- projection MLP ----------------
__global__ void proj_kernel(const float* __restrict__ inp,
                            const float* __restrict__ W0, const float* __restrict__ b0,
                            const float* __restrict__ W1, const float* __restrict__ b1,
                            float* __restrict__ f0) {
    __shared__ float hs[4][64];
    int warp = threadIdx.x >> 5, lane = threadIdx.x & 31;
    int pv = blockIdx.x * 4 + warp;
    if (pv >= VARS * N_PTS) return;
    int v = pv / N_PTS, n = pv - v * N_PTS;
    const float* x = inp + n * (VARS * 8) + v * 8;
    float xr[8];
#pragma unroll
    for (int i = 0; i < 8; i++) xr[i] = x[i];
    float a0 = b0[lane], a1 = b0[lane + 32];
#pragma unroll
    for (int i = 0; i < 8; i++) {
        a0 = fmaf(xr[i], W0[i * 64 + lane], a0);
        a1 = fmaf(xr[i], W0[i * 64 + lane + 32], a1);
    }
    hs[warp][lane]      = gelu(a0);
    hs[warp][lane + 32] = gelu(a1);
    __syncwarp();
    float acc = b1[lane];
#pragma unroll
    for (int h = 0; h < 64; h++) acc = fmaf(hs[warp][h], W1[h * 32 + lane], acc);
    f0[(size_t)pv * 32 + lane] = acc;
}

// ---------------- HMMA edge MLP ----------------
// Block: 256 threads = 8 warps; each warp processes 2 tiles of 16 edges.
// x layout per row: pos 0..3, f 4..35, zeros 36..47 (K=48, 3 k-tiles).
#define TPB 256
#define SM_BS0   51200
#define SM_BS1   51520
#define SM_BS2   51840
#define SM_XST   51968          // + warp*3072 (16 rows x 48 floats)
#define SM_SEG   76544          // + warp*64
#define SMEM_BYTES 77056

template <int MODE>
__global__ void __launch_bounds__(TPB, 2)
edge_mma_kernel(const uint8_t* __restrict__ blob,
                const float* __restrict__ b0g, const float* __restrict__ b1g,
                const float* __restrict__ b2g,
                const float* __restrict__ grid_in, const float* __restrict__ grid_out,
                const float* __restrict__ fsrc,
                const int* __restrict__ idxA, const int* __restrict__ idxB,
                float* __restrict__ outbuf, int E) {
    extern __shared__ __align__(16) uint8_t sm[];
    int tid = threadIdx.x;
    int warp = tid >> 5, lane = tid & 31;
    int g = lane >> 2;          // row group 0..7
    int t = lane & 3;           // thread-in-group
    int v = blockIdx.y;

    // stage blob + biases
    {
        const uint4* src = (const uint4*)blob;
        uint4* dst = (uint4*)sm;
        for (int i = tid; i < BLOB_BYTES / 16; i += TPB) dst[i] = src[i];
        float* bs0 = (float*)(sm + SM_BS0);
        float* bs1 = (float*)(sm + SM_BS1);
        float* bs2 = (float*)(sm + SM_BS2);
        if (tid < 80) { bs0[tid] = b0g[tid]; bs1[tid] = b1g[tid]; }
        if (tid < 32) bs2[tid] = b2g[tid];
    }
    __syncthreads();

    float* xst = (float*)(sm + SM_XST + warp * 3072);
    int*   seg_sh = (int*)(sm + SM_SEG + warp * 64);
    const float* bs0 = (const float*)(sm + SM_BS0);
    const float* bs1 = (const float*)(sm + SM_BS1);
    const float* bs2 = (const float*)(sm + SM_BS2);

#pragma unroll 1
    for (int mt = 0; mt < 2; mt++) {
        int tileBase = blockIdx.x * 256 + warp * 32 + mt * 16;

        // ---- gather: 2 lanes per edge ----
        {
            int el = lane & 15, half = lane >> 4;
            int e = tileBase + el;
            bool gv = e < E;
            int ee = gv ? e : 0;
            int jn = idxA[ee];
            int sg = (MODE == 0) ? idxB[ee] : ee / K_LAST;
            float* xrow = xst + el * 48;
            if (half == 0) {
                seg_sh[el] = gv ? sg : -1;
                float p0 = 0, p1 = 0, p2 = 0, p3 = 0;
                if (gv) {
                    p0 = grid_in[2 * jn]; p1 = grid_in[2 * jn + 1];
                    if (MODE == 0) { p2 = grid_in[2 * sg];  p3 = grid_in[2 * sg + 1]; }
                    else           { p2 = grid_out[2 * sg]; p3 = grid_out[2 * sg + 1]; }
                }
                xrow[0] = p0; xrow[1] = p1; xrow[2] = p2; xrow[3] = p3;
            }
            const float4* fp = (const float4*)(fsrc + ((size_t)v * N_PTS + jn) * 32 + half * 16);
            float4* xd = (float4*)(xrow + 4 + 16 * half);
            xd[0] = fp[0]; xd[1] = fp[1]; xd[2] = fp[2]; xd[3] = fp[3];
            if (half == 1) {
                float4 z = make_float4(0.f, 0.f, 0.f, 0.f);
                float4* zz = (float4*)(xrow + 36);
                zz[0] = z; zz[1] = z; zz[2] = z;
            }
        }
        __syncwarp();

        // ---- A1 fragments from x stage (3 k-tiles of 16) ----
        uint32_t a1h[3][4], a1l[3][4];
#pragma unroll
        for (int kt = 0; kt < 3; kt++) {
#pragma unroll
            for (int rr = 0; rr < 4; rr++) {
                int row = g + (rr & 1) * 8;
                int col = 16 * kt + 2 * t + (rr >> 1) * 8;
                u64 pv_ = *(const u64*)(xst + row * 48 + col);
                float f0, f1; unpk2(pv_, f0, f1);
                split_pack(f0, f1, a1h[kt][rr], a1l[kt][rr]);
            }
        }

        // ---- layer 1: K=48, N=80 (10 n-tiles) ----
        float d1[10][4];
#pragma unroll
        for (int nt = 0; nt < 10; nt++) {
            float* d = d1[nt];
            d[0] = 0.f; d[1] = 0.f; d[2] = 0.f; d[3] = 0.f;
#pragma unroll
            for (int kt = 0; kt < 3; kt++) {
                int set = kt * 10 + nt;
                u64 bh = *(const u64*)(sm + BL1H + (size_t)set * 256 + lane * 8);
                u64 bl = *(const u64*)(sm + BL1L + (size_t)set * 256 + lane * 8);
                uint32_t bh0 = (uint32_t)bh, bh1 = (uint32_t)(bh >> 32);
                uint32_t bl0 = (uint32_t)bl, bl1 = (uint32_t)(bl >> 32);
                mma16816(d, a1h[kt], bh0, bh1);
                mma16816(d, a1h[kt], bl0, bl1);
                mma16816(d, a1l[kt], bh0, bh1);
            }
        }

        // ---- epilogue 1: bias + gelu + split -> A2 fragments ----
        uint32_t a2h[5][4], a2l[5][4];
#pragma unroll
        for (int m = 0; m < 5; m++) {
            int j0 = 2 * m, j1 = 2 * m + 1;
            float bb0, bb1, bb2, bb3;
            unpk2(*(const u64*)(bs0 + 8 * j0 + 2 * t), bb0, bb1);
            unpk2(*(const u64*)(bs0 + 8 * j1 + 2 * t), bb2, bb3);
            float q0, q1;
            unpk2(gelu2(pk2(d1[j0][0] + bb0, d1[j0][1] + bb1)), q0, q1);
            split_pack(q0, q1, a2h[m][0], a2l[m][0]);
            unpk2(gelu2(pk2(d1[j0][2] + bb0, d1[j0][3] + bb1)), q0, q1);
            split_pack(q0, q1, a2h[m][1], a2l[m][1]);
            unpk2(gelu2(pk2(d1[j1][0] + bb2, d1[j1][1] + bb3)), q0, q1);
            split_pack(q0, q1, a2h[m][2], a2l[m][2]);
            unpk2(gelu2(pk2(d1[j1][2] + bb2, d1[j1][3] + bb3)), q0, q1);
            split_pack(q0, q1, a2h[m][3], a2l[m][3]);
        }

        // ---- layer 2: K=80, N=80 ----
        float d2[10][4];
#pragma unroll
        for (int nt = 0; nt < 10; nt++) {
            float* d = d2[nt];
            d[0] = 0.f; d[1] = 0.f; d[2] = 0.f; d[3] = 0.f;
#pragma unroll
            for (int kt = 0; kt < 5; kt++) {
                int set = kt * 10 + nt;
                u64 bh = *(const u64*)(sm + BL2H + (size_t)set * 256 + lane * 8);
                u64 bl = *(const u64*)(sm + BL2L + (size_t)set * 256 + lane * 8);
                uint32_t bh0 = (uint32_t)bh, bh1 = (uint32_t)(bh >> 32);
                uint32_t bl0 = (uint32_t)bl, bl1 = (uint32_t)(bl >> 32);
                mma16816(d, a2h[kt], bh0, bh1);
                mma16816(d, a2h[kt], bl0, bl1);
                mma16816(d, a2l[kt], bh0, bh1);
            }
        }

        // ---- epilogue 2 -> A3 fragments ----
        uint32_t a3h[5][4], a3l[5][4];
#pragma unroll
        for (int m = 0; m < 5; m++) {
            int j0 = 2 * m, j1 = 2 * m + 1;
            float bb0, bb1, bb2, bb3;
            unpk2(*(const u64*)(bs1 + 8 * j0 + 2 * t), bb0, bb1);
            unpk2(*(const u64*)(bs1 + 8 * j1 + 2 * t), bb2, bb3);
            float q0, q1;
            unpk2(gelu2(pk2(d2[j0][0] + bb0, d2[j0][1] + bb1)), q0, q1);
            split_pack(q0, q1, a3h[m][0], a3l[m][0]);
            unpk2(gelu2(pk2(d2[j0][2] + bb0, d2[j0][3] + bb1)), q0, q1);
            split_pack(q0, q1, a3h[m][1], a3l[m][1]);
            unpk2(gelu2(pk2(d2[j1][0] + bb2, d2[j1][1] + bb3)), q0, q1);
            split_pack(q0, q1, a3h[m][2], a3l[m][2]);
            unpk2(gelu2(pk2(d2[j1][2] + bb2, d2[j1][3] + bb3)), q0, q1);
            split_pack(q0, q1, a3h[m][3], a3l[m][3]);
        }

        // ---- layer 3: K=80, N=32 (4 n-tiles) ----
        float d3[4][4];
#pragma unroll
        for (int nt = 0; nt < 4; nt++) {
            float* d = d3[nt];
            d[0] = 0.f; d[1] = 0.f; d[2] = 0.f; d[3] = 0.f;
#pragma unroll
            for (int kt = 0; kt < 5; kt++) {
                int set = kt * 4 + nt;
                u64 bh = *(const u64*)(sm + BL3H + (size_t)set * 256 + lane * 8);
                u64 bl = *(const u64*)(sm + BL3L + (size_t)set * 256 + lane * 8);
                uint32_t bh0 = (uint32_t)bh, bh1 = (uint32_t)(bh >> 32);
                uint32_t bl0 = (uint32_t)bl, bl1 = (uint32_t)(bl >> 32);
                mma16816(d, a3h[kt], bh0, bh1);
                mma16816(d, a3h[kt], bl0, bl1);
                mma16816(d, a3l[kt], bh0, bh1);
            }
        }

        // ---- epilogue 3: bias + scatter (rows g and g+8) ----
        {
            int sg0 = seg_sh[g], sg1 = seg_sh[g + 8];
            float scale = (MODE == 0) ? 1.0f : 0.1f;
            float* dst0 = nullptr; float* dst1 = nullptr;
            if (MODE == 0) {
                if (sg0 >= 0) dst0 = outbuf + ((size_t)v * N_PTS + sg0) * 32;
                if (sg1 >= 0) dst1 = outbuf + ((size_t)v * N_PTS + sg1) * 32;
            } else {
                if (sg0 >= 0) dst0 = outbuf + (size_t)sg0 * (VARS * 32) + v * 32;
                if (sg1 >= 0) dst1 = outbuf + (size_t)sg1 * (VARS * 32) + v * 32;
            }
#pragma unroll
            for (int nt = 0; nt < 4; nt++) {
                float bb0, bb1;
                unpk2(*(const u64*)(bs2 + 8 * nt + 2 * t), bb0, bb1);
                int c0 = 8 * nt + 2 * t;
                if (dst0) {
                    atomicAdd(dst0 + c0,     (d3[nt][0] + bb0) * scale);
                    atomicAdd(dst0 + c0 + 1, (d3[nt][1] + bb1) * scale);
                }
                if (dst1) {
                    atomicAdd(dst1 + c0,     (d3[nt][2] + bb0) * scale);
                    atomicAdd(dst1 + c0 + 1, (d3[nt][3] + bb1) * scale);
                }
            }
        }
        __syncwarp();
    }
}

// f1 = segment_sum * inv_count + f0 (in place)
__global__ void f1_kernel(float* __restrict__ f0, const float* __restrict__ acc,
                          const int* __restrict__ counts) {
    int idx = blockIdx.x * 256 + threadIdx.x;
    if (idx >= VARS * N_PTS * 32) return;
    int n = (idx >> 5) % N_PTS;
    int c = counts[n];
    float inv = 1.0f / (float)(c > 1 ? c : 1);
    f0[idx] = fmaf(acc[idx], inv, f0[idx]);
}

extern "C" void kernel_launch(void* const* d_in, const int* in_sizes, int n_in,
                              void* d_out, int out_size) {
    const float* inp   = (const float*)d_in[0];
    const float* gin   = (const float*)d_in[1];
    const float* gout  = (const float*)d_in[2];
    const float* pW0   = (const float*)d_in[3];
    const float* pb0   = (const float*)d_in[4];
    const float* pW1   = (const float*)d_in[5];
    const float* pb1   = (const float*)d_in[6];
    const float* i0W0  = (const float*)d_in[7];
    const float* i0b0  = (const float*)d_in[8];
    const float* i0W1  = (const float*)d_in[9];
    const float* i0b1  = (const float*)d_in[10];
    const float* i0W2  = (const float*)d_in[11];
    const float* i0b2  = (const float*)d_in[12];
    const float* i1W0  = (const float*)d_in[13];
    const float* i1b0  = (const float*)d_in[14];
    const float* i1W1  = (const float*)d_in[15];
    const float* i1b1  = (const float*)d_in[16];
    const float* i1W2  = (const float*)d_in[17];
    const float* i1b2  = (const float*)d_in[18];
    const int* nbr_index  = (const int*)d_in[19];
    const int* nbr_seg    = (const int*)d_in[20];
    const int* nbr_counts = (const int*)d_in[21];
    const int* nbr_last   = (const int*)d_in[22];
    int E = in_sizes[19];

    float *f0, *acc;
    uint8_t* blob;
    cudaGetSymbolAddress((void**)&f0,   g_f0);
    cudaGetSymbolAddress((void**)&acc,  g_acc);
    cudaGetSymbolAddress((void**)&blob, g_blob);
    uint8_t* blob0 = blob;
    uint8_t* blob1 = blob + BLOB_BYTES;

    cudaMemsetAsync(acc, 0, sizeof(float) * VARS * N_PTS * 32);
    cudaMemsetAsync(d_out, 0, sizeof(float) * (size_t)out_size);

    // single fused prep launch (both phases, all 3 layers)
    prep_all_kernel<<<(2 * 100 * 32 + 255) / 256, 256>>>(i0W0, i0W1, i0W2,
                                                         i1W0, i1W1, i1W2, blob0, blob1);

    proj_kernel<<<(VARS * N_PTS + 3) / 4, 128>>>(inp, pW0, pb0, pW1, pb1, f0);

    cudaFuncSetAttribute(edge_mma_kernel<0>, cudaFuncAttributeMaxDynamicSharedMemorySize, SMEM_BYTES);
    cudaFuncSetAttribute(edge_mma_kernel<1>, cudaFuncAttributeMaxDynamicSharedMemorySize, SMEM_BYTES);

    dim3 g1((unsigned)((E + 255) / 256), VARS);
    edge_mma_kernel<0><<<g1, TPB, SMEM_BYTES>>>(blob0, i0b0, i0b1, i0b2,
                                                gin, nullptr, f0, nbr_index, nbr_seg, acc, E);

    f1_kernel<<<(VARS * N_PTS * 32 + 255) / 256, 256>>>(f0, acc, nbr_counts);

    int E2 = M_PTS * K_LAST;
    dim3 g2((unsigned)((E2 + 255) / 256), VARS);
    edge_mma_kernel<1><<<g2, TPB, SMEM_BYTES>>>(blob1, i1b0, i1b1, i1b2,
                                                gin, gout, f0, nbr_last, nullptr, (float*)d_out, E2);
}

// round 12
// speedup vs baseline: 1.0938x; 1.0731x over previous
#include <cuda_runtime.h>
#include <cuda_bf16.h>
#include <math.h>
#include <stdint.h>

#define N_PTS 8192
#define M_PTS 2048
#define K_LAST 10
#define VARS 3

typedef unsigned long long u64;

// ---------------- packed f32x2 helpers ----------------
__device__ __forceinline__ u64 pk2(float lo, float hi) {
    u64 r; asm("mov.b64 %0,{%1,%2};" : "=l"(r) : "f"(lo), "f"(hi)); return r;
}
__device__ __forceinline__ void unpk2(u64 v, float& lo, float& hi) {
    asm("mov.b64 {%0,%1},%2;" : "=f"(lo), "=f"(hi) : "l"(v));
}
__device__ __forceinline__ u64 f2fma(u64 a, u64 b, u64 c) {
    u64 d; asm("fma.rn.f32x2 %0,%1,%2,%3;" : "=l"(d) : "l"(a), "l"(b), "l"(c)); return d;
}
__device__ __forceinline__ u64 f2mul(u64 a, u64 b) {
    u64 d; asm("mul.rn.f32x2 %0,%1,%2;" : "=l"(d) : "l"(a), "l"(b)); return d;
}
__device__ __forceinline__ u64 dup2(float x) { return pk2(x, x); }

__device__ __forceinline__ float gelu(float x) {
    return 0.5f * x * (1.0f + erff(x * 0.70710678118654752f));
}

// packed GELU (A&S 7.1.26 erf, abs err <= 1.5e-7)
__device__ __forceinline__ u64 gelu2(u64 x) {
    u64 ax = x & 0x7FFFFFFF7FFFFFFFULL;
    u64 z  = f2mul(ax, dup2(0.70710678118654752f));
    u64 den = f2fma(z, dup2(0.3275911f), dup2(1.0f));
    float dl, dh, rl, rh;
    unpk2(den, dl, dh);
    asm("rcp.approx.f32 %0,%1;" : "=f"(rl) : "f"(dl));
    asm("rcp.approx.f32 %0,%1;" : "=f"(rh) : "f"(dh));
    u64 t = pk2(rl, rh);
    u64 z2 = f2mul(z, z);
    u64 m  = f2mul(z2, dup2(-1.4426950408889634f));
    float ml, mh, el, eh;
    unpk2(m, ml, mh);
    asm("ex2.approx.f32 %0,%1;" : "=f"(el) : "f"(ml));
    asm("ex2.approx.f32 %0,%1;" : "=f"(eh) : "f"(mh));
    u64 e = pk2(el, eh);
    u64 p = f2fma(t, dup2(1.061405429f), dup2(-1.453152027f));
    p = f2fma(p, t, dup2(1.421413741f));
    p = f2fma(p, t, dup2(-0.284496736f));
    p = f2fma(p, t, dup2(0.254829592f));
    p = f2mul(p, t);
    u64 np = p ^ 0x8000000080000000ULL;
    u64 u  = f2fma(np, e, dup2(1.0f));
    u64 E  = u | (x & 0x8000000080000000ULL);
    u64 h  = f2fma(E, dup2(0.5f), dup2(0.5f));
    return f2mul(x, h);
}

// pack two floats to bf16x2 (a -> low 16 bits, b -> high)
__device__ __forceinline__ uint32_t pack_bf16(float a, float b) {
    uint32_t r; asm("cvt.rn.bf16x2.f32 %0, %1, %2;" : "=r"(r) : "f"(b), "f"(a));
    return r;
}
// split f32 pair into (hi bf16x2, lo bf16x2)
__device__ __forceinline__ void split_pack(float f0, float f1, uint32_t& hi, uint32_t& lo) {
    hi = pack_bf16(f0, f1);
    float h0 = __uint_as_float(hi << 16);
    float h1 = __uint_as_float(hi & 0xFFFF0000u);
    lo = pack_bf16(f0 - h0, f1 - h1);
}

// m16n8k16 bf16 MMA, D (f32) accumulate in place
__device__ __forceinline__ void mma16816(float* d, const uint32_t* a, uint32_t b0, uint32_t b1) {
    asm volatile(
        "mma.sync.aligned.m16n8k16.row.col.f32.bf16.bf16.f32 "
        "{%0,%1,%2,%3}, {%4,%5,%6,%7}, {%8,%9}, {%0,%1,%2,%3};"
        : "+f"(d[0]), "+f"(d[1]), "+f"(d[2]), "+f"(d[3])
        : "r"(a[0]), "r"(a[1]), "r"(a[2]), "r"(a[3]), "r"(b0), "r"(b1));
}

// ---------------- scratch ----------------
__device__ float g_f0[VARS * N_PTS * 32];
__device__ float g_acc[VARS * N_PTS * 32];
__device__ uint8_t g_blob[2][51200];
// interleaved blob: per set 512B, lane entry = uint4 {bh0, bh1, bl0, bl1}
#define BL1 0        // 30 sets * 512
#define BL2 15360    // 50 sets * 512
#define BL3 40960    // 20 sets * 512
#define BLOB_BYTES 51200

// ---------------- fused weight prep (both phases, all layers) ----------------
// Fragment set (kt,nt): lane holds n = nt*8+lane/4, k0 = kt*16+2*(lane%4):
// reg0={W[k0][n],W[k0+1][n]}, reg1={W[k0+8][n],W[k0+9][n]}.
__global__ void prep_all_kernel(const float* __restrict__ W10, const float* __restrict__ W11,
                                const float* __restrict__ W12,
                                const float* __restrict__ W20, const float* __restrict__ W21,
                                const float* __restrict__ W22,
                                uint8_t* __restrict__ blob0, uint8_t* __restrict__ blob1) {
    int idx = blockIdx.x * 256 + threadIdx.x;
    if (idx >= 2 * 100 * 32) return;
    int lane = idx & 31;
    int set = (idx >> 5) % 100;
    int phase = (idx >> 5) / 100;
    uint8_t* blob = phase ? blob1 : blob0;

    const float* W; int NT, N, Kreal, sl, ob;
    if (set < 30)      { W = phase ? W20 : W10; NT = 10; N = 80; Kreal = 36; sl = set;      ob = BL1; }
    else if (set < 80) { W = phase ? W21 : W11; NT = 10; N = 80; Kreal = 80; sl = set - 30; ob = BL2; }
    else               { W = phase ? W22 : W12; NT = 4;  N = 32; Kreal = 80; sl = set - 80; ob = BL3; }

    int kt = sl / NT, nt = sl - kt * NT;
    int n = nt * 8 + (lane >> 2);
    int k0 = kt * 16 + 2 * (lane & 3);
    float v[4];
#pragma unroll
    for (int j = 0; j < 4; j++) {
        int k = k0 + (j >> 1) * 8 + (j & 1);
        v[j] = (k < Kreal) ? W[k * N + n] : 0.f;
    }
    uint32_t h0, l0, h1, l1;
    split_pack(v[0], v[1], h0, l0);
    split_pack(v[2], v[3], h1, l1);
    *(uint4*)(blob + ob + (size_t)sl * 512 + lane * 16) = make_uint4(h0, h1, l0, l1);
}

// ---------------- projection MLP ----------------
__global__ void proj_kernel(const float* __restrict__ inp,
                            const float* __restrict__ W0, const float* __restrict__ b0,
                            const float* __restrict__ W1, const float* __restrict__ b1,
                            float* __restrict__ f0) {
    __shared__ float hs[4][64];
    int warp = threadIdx.x >> 5, lane = threadIdx.x & 31;
    int pv = blockIdx.x * 4 + warp;
    if (pv >= VARS * N_PTS) return;
    int v = pv / N_PTS, n = pv - v * N_PTS;
    const float* x = inp + n * (VARS * 8) + v * 8;
    float xr[8];
#pragma unroll
    for (int i = 0; i < 8; i++) xr[i] = x[i];
    float a0 = b0[lane], a1 = b0[lane + 32];
#pragma unroll
    for (int i = 0; i < 8; i++) {
        a0 = fmaf(xr[i], W0[i * 64 + lane], a0);
        a1 = fmaf(xr[i], W0[i * 64 + lane + 32], a1);
    }
    hs[warp][lane]      = gelu(a0);
    hs[warp][lane + 32] = gelu(a1);
    __syncwarp();
    float acc = b1[lane];
#pragma unroll
    for (int h = 0; h < 64; h++) acc = fmaf(hs[warp][h], W1[h * 32 + lane], acc);
    f0[(size_t)pv * 32 + lane] = acc;
}

// ---------------- HMMA edge MLP ----------------
// Block: 128 threads = 4 warps; each warp processes 2 tiles of 16 edges.
// x layout per row: pos 0..3, f 4..35, zeros 36..47 (K=48, 3 k-tiles).
#define TPB 128
#define SM_BS0   51200
#define SM_BS1   51520
#define SM_BS2   51840
#define SM_XST   51968          // + warp*3072 (16 rows x 48 floats)
#define SM_SEG   64256          // + warp*64
#define SMEM_BYTES 64512

template <int MODE>
__global__ void __launch_bounds__(TPB, 3)
edge_mma_kernel(const uint8_t* __restrict__ blob,
                const float* __restrict__ b0g, const float* __restrict__ b1g,
                const float* __restrict__ b2g,
                const float* __restrict__ grid_in, const float* __restrict__ grid_out,
                const float* __restrict__ fsrc,
                const int* __restrict__ idxA, const int* __restrict__ idxB,
                float* __restrict__ outbuf, int E) {
    extern __shared__ __align__(16) uint8_t sm[];
    int tid = threadIdx.x;
    int warp = tid >> 5, lane = tid & 31;
    int g = lane >> 2;          // row group 0..7
    int t = lane & 3;           // thread-in-group
    int v = blockIdx.y;

    // stage blob + biases
    {
        const uint4* src = (const uint4*)blob;
        uint4* dst = (uint4*)sm;
        for (int i = tid; i < BLOB_BYTES / 16; i += TPB) dst[i] = src[i];
        float* bs0 = (float*)(sm + SM_BS0);
        float* bs1 = (float*)(sm + SM_BS1);
        float* bs2 = (float*)(sm + SM_BS2);
        if (tid < 80) { bs0[tid] = b0g[tid]; bs1[tid] = b1g[tid]; }
        if (tid < 32) bs2[tid] = b2g[tid];
    }
    __syncthreads();

    float* xst = (float*)(sm + SM_XST + warp * 3072);
    int*   seg_sh = (int*)(sm + SM_SEG + warp * 64);
    const float* bs0 = (const float*)(sm + SM_BS0);
    const float* bs1 = (const float*)(sm + SM_BS1);
    const float* bs2 = (const float*)(sm + SM_BS2);

#pragma unroll 1
    for (int mt = 0; mt < 2; mt++) {
        int tileBase = blockIdx.x * 128 + warp * 32 + mt * 16;

        // ---- gather: 2 lanes per edge ----
        {
            int el = lane & 15, half = lane >> 4;
            int e = tileBase + el;
            bool gv = e < E;
            int ee = gv ? e : 0;
            int jn = idxA[ee];
            int sg = (MODE == 0) ? idxB[ee] : ee / K_LAST;
            float* xrow = xst + el * 48;
            if (half == 0) {
                seg_sh[el] = gv ? sg : -1;
                float p0 = 0, p1 = 0, p2 = 0, p3 = 0;
                if (gv) {
                    p0 = grid_in[2 * jn]; p1 = grid_in[2 * jn + 1];
                    if (MODE == 0) { p2 = grid_in[2 * sg];  p3 = grid_in[2 * sg + 1]; }
                    else           { p2 = grid_out[2 * sg]; p3 = grid_out[2 * sg + 1]; }
                }
                xrow[0] = p0; xrow[1] = p1; xrow[2] = p2; xrow[3] = p3;
            }
            const float4* fp = (const float4*)(fsrc + ((size_t)v * N_PTS + jn) * 32 + half * 16);
            float4* xd = (float4*)(xrow + 4 + 16 * half);
            xd[0] = fp[0]; xd[1] = fp[1]; xd[2] = fp[2]; xd[3] = fp[3];
            if (half == 1) {
                float4 z = make_float4(0.f, 0.f, 0.f, 0.f);
                float4* zz = (float4*)(xrow + 36);
                zz[0] = z; zz[1] = z; zz[2] = z;
            }
        }
        __syncwarp();

        // ---- A1 fragments from x stage (3 k-tiles of 16) ----
        uint32_t a1h[3][4], a1l[3][4];
#pragma unroll
        for (int kt = 0; kt < 3; kt++) {
#pragma unroll
            for (int rr = 0; rr < 4; rr++) {
                int row = g + (rr & 1) * 8;
                int col = 16 * kt + 2 * t + (rr >> 1) * 8;
                u64 pv_ = *(const u64*)(xst + row * 48 + col);
                float f0, f1; unpk2(pv_, f0, f1);
                split_pack(f0, f1, a1h[kt][rr], a1l[kt][rr]);
            }
        }

        // ---- layer 1: K=48, N=80 (10 n-tiles), 1 LDS.128 per (kt,nt) ----
        float d1[10][4];
#pragma unroll
        for (int nt = 0; nt < 10; nt++) {
            float* d = d1[nt];
            d[0] = 0.f; d[1] = 0.f; d[2] = 0.f; d[3] = 0.f;
#pragma unroll
            for (int kt = 0; kt < 3; kt++) {
                int set = kt * 10 + nt;
                uint4 q = *(const uint4*)(sm + BL1 + (size_t)set * 512 + lane * 16);
                mma16816(d, a1h[kt], q.x, q.y);
                mma16816(d, a1h[kt], q.z, q.w);
                mma16816(d, a1l[kt], q.x, q.y);
            }
        }

        // ---- epilogue 1: bias + gelu + split -> A2 fragments ----
        uint32_t a2h[5][4], a2l[5][4];
#pragma unroll
        for (int m = 0; m < 5; m++) {
            int j0 = 2 * m, j1 = 2 * m + 1;
            float bb0, bb1, bb2, bb3;
            unpk2(*(const u64*)(bs0 + 8 * j0 + 2 * t), bb0, bb1);
            unpk2(*(const u64*)(bs0 + 8 * j1 + 2 * t), bb2, bb3);
            float q0, q1;
            unpk2(gelu2(pk2(d1[j0][0] + bb0, d1[j0][1] + bb1)), q0, q1);
            split_pack(q0, q1, a2h[m][0], a2l[m][0]);
            unpk2(gelu2(pk2(d1[j0][2] + bb0, d1[j0][3] + bb1)), q0, q1);
            split_pack(q0, q1, a2h[m][1], a2l[m][1]);
            unpk2(gelu2(pk2(d1[j1][0] + bb2, d1[j1][1] + bb3)), q0, q1);
            split_pack(q0, q1, a2h[m][2], a2l[m][2]);
            unpk2(gelu2(pk2(d1[j1][2] + bb2, d1[j1][3] + bb3)), q0, q1);
            split_pack(q0, q1, a2h[m][3], a2l[m][3]);
        }

        // ---- layer 2: K=80, N=80 ----
        float d2[10][4];
#pragma unroll
        for (int nt = 0; nt < 10; nt++) {
            float* d = d2[nt];
            d[0] = 0.f; d[1] = 0.f; d[2] = 0.f; d[3] = 0.f;
#pragma unroll
            for (int kt = 0; kt < 5; kt++) {
                int set = kt * 10 + nt;
                uint4 q = *(const uint4*)(sm + BL2 + (size_t)set * 512 + lane * 16);
                mma16816(d, a2h[kt], q.x, q.y);
                mma16816(d, a2h[kt], q.z, q.w);
                mma16816(d, a2l[kt], q.x, q.y);
            }
        }

        // ---- epilogue 2 -> A3 fragments ----
        uint32_t a3h[5][4], a3l[5][4];
#pragma unroll
        for (int m = 0; m < 5; m++) {
            int j0 = 2 * m, j1 = 2 * m + 1;
            float bb0, bb1, bb2, bb3;
            unpk2(*(const u64*)(bs1 + 8 * j0 + 2 * t), bb0, bb1);
            unpk2(*(const u64*)(bs1 + 8 * j1 + 2 * t), bb2, bb3);
            float q0, q1;
            unpk2(gelu2(pk2(d2[j0][0] + bb0, d2[j0][1] + bb1)), q0, q1);
            split_pack(q0, q1, a3h[m][0], a3l[m][0]);
            unpk2(gelu2(pk2(d2[j0][2] + bb0, d2[j0][3] + bb1)), q0, q1);
            split_pack(q0, q1, a3h[m][1], a3l[m][1]);
            unpk2(gelu2(pk2(d2[j1][0] + bb2, d2[j1][1] + bb3)), q0, q1);
            split_pack(q0, q1, a3h[m][2], a3l[m][2]);
            unpk2(gelu2(pk2(d2[j1][2] + bb2, d2[j1][3] + bb3)), q0, q1);
            split_pack(q0, q1, a3h[m][3], a3l[m][3]);
        }

        // ---- layer 3: K=80, N=32 (4 n-tiles) ----
        float d3[4][4];
#pragma unroll
        for (int nt = 0; nt < 4; nt++) {
            float* d = d3[nt];
            d[0] = 0.f; d[1] = 0.f; d[2] = 0.f; d[3] = 0.f;
#pragma unroll
            for (int kt = 0; kt < 5; kt++) {
                int set = kt * 4 + nt;
                uint4 q = *(const uint4*)(sm + BL3 + (size_t)set * 512 + lane * 16);
                mma16816(d, a3h[kt], q.x, q.y);
                mma16816(d, a3h[kt], q.z, q.w);
                mma16816(d, a3l[kt], q.x, q.y);
            }
        }

        // ---- epilogue 3: bias + scatter (rows g and g+8) ----
        {
            int sg0 = seg_sh[g], sg1 = seg_sh[g + 8];
            float scale = (MODE == 0) ? 1.0f : 0.1f;
            float* dst0 = nullptr; float* dst1 = nullptr;
            if (MODE == 0) {
                if (sg0 >= 0) dst0 = outbuf + ((size_t)v * N_PTS + sg0) * 32;
                if (sg1 >= 0) dst1 = outbuf + ((size_t)v * N_PTS + sg1) * 32;
            } else {
                if (sg0 >= 0) dst0 = outbuf + (size_t)sg0 * (VARS * 32) + v * 32;
                if (sg1 >= 0) dst1 = outbuf + (size_t)sg1 * (VARS * 32) + v * 32;
            }
#pragma unroll
            for (int nt = 0; nt < 4; nt++) {
                float bb0, bb1;
                unpk2(*(const u64*)(bs2 + 8 * nt + 2 * t), bb0, bb1);
                int c0 = 8 * nt + 2 * t;
                if (dst0) {
                    atomicAdd(dst0 + c0,     (d3[nt][0] + bb0) * scale);
                    atomicAdd(dst0 + c0 + 1, (d3[nt][1] + bb1) * scale);
                }
                if (dst1) {
                    atomicAdd(dst1 + c0,     (d3[nt][2] + bb0) * scale);
                    atomicAdd(dst1 + c0 + 1, (d3[nt][3] + bb1) * scale);
                }
            }
        }
        __syncwarp();
    }
}

// f1 = segment_sum * inv_count + f0 (in place)
__global__ void f1_kernel(float* __restrict__ f0, const float* __restrict__ acc,
                          const int* __restrict__ counts) {
    int idx = blockIdx.x * 256 + threadIdx.x;
    if (idx >= VARS * N_PTS * 32) return;
    int n = (idx >> 5) % N_PTS;
    int c = counts[n];
    float inv = 1.0f / (float)(c > 1 ? c : 1);
    f0[idx] = fmaf(acc[idx], inv, f0[idx]);
}

extern "C" void kernel_launch(void* const* d_in, const int* in_sizes, int n_in,
                              void* d_out, int out_size) {
    const float* inp   = (const float*)d_in[0];
    const float* gin   = (const float*)d_in[1];
    const float* gout  = (const float*)d_in[2];
    const float* pW0   = (const float*)d_in[3];
    const float* pb0   = (const float*)d_in[4];
    const float* pW1   = (const float*)d_in[5];
    const float* pb1   = (const float*)d_in[6];
    const float* i0W0  = (const float*)d_in[7];
    const float* i0b0  = (const float*)d_in[8];
    const float* i0W1  = (const float*)d_in[9];
    const float* i0b1  = (const float*)d_in[10];
    const float* i0W2  = (const float*)d_in[11];
    const float* i0b2  = (const float*)d_in[12];
    const float* i1W0  = (const float*)d_in[13];
    const float* i1b0  = (const float*)d_in[14];
    const float* i1W1  = (const float*)d_in[15];
    const float* i1b1  = (const float*)d_in[16];
    const float* i1W2  = (const float*)d_in[17];
    const float* i1b2  = (const float*)d_in[18];
    const int* nbr_index  = (const int*)d_in[19];
    const int* nbr_seg    = (const int*)d_in[20];
    const int* nbr_counts = (const int*)d_in[21];
    const int* nbr_last   = (const int*)d_in[22];
    int E = in_sizes[19];

    float *f0, *acc;
    uint8_t* blob;
    cudaGetSymbolAddress((void**)&f0,   g_f0);
    cudaGetSymbolAddress((void**)&acc,  g_acc);
    cudaGetSymbolAddress((void**)&blob, g_blob);
    uint8_t* blob0 = blob;
    uint8_t* blob1 = blob + BLOB_BYTES;

    cudaMemsetAsync(acc, 0, sizeof(float) * VARS * N_PTS * 32);
    cudaMemsetAsync(d_out, 0, sizeof(float) * (size_t)out_size);

    // single fused prep launch (both phases, all 3 layers)
    prep_all_kernel<<<(2 * 100 * 32 + 255) / 256, 256>>>(i0W0, i0W1, i0W2,
                                                         i1W0, i1W1, i1W2, blob0, blob1);

    proj_kernel<<<(VARS * N_PTS + 3) / 4, 128>>>(inp, pW0, pb0, pW1, pb1, f0);

    cudaFuncSetAttribute(edge_mma_kernel<0>, cudaFuncAttributeMaxDynamicSharedMemorySize, SMEM_BYTES);
    cudaFuncSetAttribute(edge_mma_kernel<1>, cudaFuncAttributeMaxDynamicSharedMemorySize, SMEM_BYTES);

    dim3 g1((unsigned)((E + 127) / 128), VARS);
    edge_mma_kernel<0><<<g1, TPB, SMEM_BYTES>>>(blob0, i0b0, i0b1, i0b2,
                                                gin, nullptr, f0, nbr_index, nbr_seg, acc, E);

    f1_kernel<<<(VARS * N_PTS * 32 + 255) / 256, 256>>>(f0, acc, nbr_counts);

    int E2 = M_PTS * K_LAST;
    dim3 g2((unsigned)((E2 + 127) / 128), VARS);
    edge_mma_kernel<1><<<g2, TPB, SMEM_BYTES>>>(blob1, i1b0, i1b1, i1b2,
                                                gin, gout, f0, nbr_last, nullptr, (float*)d_out, E2);
}